// round 1
// baseline (speedup 1.0000x reference)
#include <cuda_runtime.h>
#include <cuda_bf16.h>

// Problem: B=2, C=4, D=64, H=256, W=256
#define Ww   256
#define HW   65536        // H*W
#define DHW  4194304      // D*H*W
#define DHW4 1048576      // DHW/4
#define NQ   2097152      // B*DHW/4  (threads, 4 voxels each)
#define NELEM 25165824.0  // B*(C-1)*DHW

// Scratch: softmax probs for classes 1..3, layout (B, 3, D, H, W). 100.7 MB.
__device__ __align__(16) float g_probs[2 * 3 * DHW];
__device__ double g_acc;

__global__ void zero_acc_kernel() { g_acc = 0.0; }

// Pass 1: per-voxel softmax over C=4, keep classes 1..3. 4 voxels/thread (float4).
__global__ void softmax_kernel(const float* __restrict__ logits) {
    int t = blockIdx.x * blockDim.x + threadIdx.x;
    if (t >= NQ) return;
    int b  = t >> 20;           // t / DHW4
    int v4 = t & (DHW4 - 1);
    const float4* L = (const float4*)logits + (size_t)b * 4 * DHW4 + v4;
    float4 x0 = L[0 * DHW4];
    float4 x1 = L[1 * DHW4];
    float4 x2 = L[2 * DHW4];
    float4 x3 = L[3 * DHW4];
    float4 p1, p2, p3;
#define SM1(comp) {                                                       \
        float a = x0.comp, bb = x1.comp, c = x2.comp, dd = x3.comp;       \
        float m  = fmaxf(fmaxf(a, bb), fmaxf(c, dd));                     \
        float e0 = __expf(a - m), e1 = __expf(bb - m);                    \
        float e2 = __expf(c - m), e3 = __expf(dd - m);                    \
        float inv = __frcp_rn(e0 + e1 + e2 + e3);                         \
        p1.comp = e1 * inv; p2.comp = e2 * inv; p3.comp = e3 * inv; }
    SM1(x) SM1(y) SM1(z) SM1(w)
#undef SM1
    float4* P = (float4*)g_probs + (size_t)b * 3 * DHW4 + v4;
    P[0 * DHW4] = p1;
    P[1 * DHW4] = p2;
    P[2 * DHW4] = p3;
}

__device__ __forceinline__ float f4get(const float4& f, int j) {
    switch (j) { case 0: return f.x; case 1: return f.y; case 2: return f.z; default: return f.w; }
}
__device__ __forceinline__ int i4get(const int4& f, int j) {
    switch (j) { case 0: return f.x; case 1: return f.y; case 2: return f.z; default: return f.w; }
}

// Pass 2: |Laplacian(probs)| vs |Laplacian(one-hot targets)|, squared diff, reduce.
// Zero padding: out-of-bounds neighbors contribute 0; center weight is always -6.
__global__ void loss_kernel(const int* __restrict__ targets) {
    int t = blockIdx.x * blockDim.x + threadIdx.x;
    float acc = 0.f;
    if (t < NQ) {
        int w4 = t & 63;
        int h  = (t >> 6) & 255;
        int d  = (t >> 14) & 63;
        int b  = t >> 20;
        int v  = d * HW + h * Ww + (w4 << 2);

        const float* Pb = g_probs + (size_t)b * 3 * DHW;
        const int*   Tb = targets + (size_t)b * DHW;
        const float4 zf = make_float4(0.f, 0.f, 0.f, 0.f);
        const int4   zi = make_int4(0, 0, 0, 0);

        float4 Cn[3], Dm[3], Dp[3], Hm[3], Hp[3];
        float  Lw[3], Rw[3];
#pragma unroll
        for (int c = 0; c < 3; c++) {
            const float* base = Pb + c * DHW + v;
            Cn[c] = *(const float4*)base;
            Dm[c] = (d > 0)    ? *(const float4*)(base - HW) : zf;
            Dp[c] = (d < 63)   ? *(const float4*)(base + HW) : zf;
            Hm[c] = (h > 0)    ? *(const float4*)(base - Ww) : zf;
            Hp[c] = (h < 255)  ? *(const float4*)(base + Ww) : zf;
            Lw[c] = (w4 > 0)   ? base[-1] : 0.f;
            Rw[c] = (w4 < 63)  ? base[4]  : 0.f;
        }
        const int* tb = Tb + v;
        int4 tC  = *(const int4*)tb;
        int4 tDm = (d > 0)    ? *(const int4*)(tb - HW) : zi;
        int4 tDp = (d < 63)   ? *(const int4*)(tb + HW) : zi;
        int4 tHm = (h > 0)    ? *(const int4*)(tb - Ww) : zi;
        int4 tHp = (h < 255)  ? *(const int4*)(tb + Ww) : zi;
        int  tL  = (w4 > 0)   ? tb[-1] : 0;
        int  tR  = (w4 < 63)  ? tb[4]  : 0;

#pragma unroll
        for (int j = 0; j < 4; j++) {
            int tc  = i4get(tC, j);
            int tl  = (j == 0) ? tL : i4get(tC, j - 1);
            int tr  = (j == 3) ? tR : i4get(tC, j + 1);
            int td0 = i4get(tDm, j), td1 = i4get(tDp, j);
            int th0 = i4get(tHm, j), th1 = i4get(tHp, j);
#pragma unroll
            for (int c = 0; c < 3; c++) {
                float pl = (j == 0) ? Lw[c] : f4get(Cn[c], j - 1);
                float pr = (j == 3) ? Rw[c] : f4get(Cn[c], j + 1);
                float lap_p = f4get(Dm[c], j) + f4get(Dp[c], j)
                            + f4get(Hm[c], j) + f4get(Hp[c], j)
                            + pl + pr - 6.f * f4get(Cn[c], j);
                int c1  = c + 1;
                int cnt = (td0 == c1) + (td1 == c1) + (th0 == c1) + (th1 == c1)
                        + (tl == c1) + (tr == c1);
                float lap_t = (float)(cnt - 6 * (tc == c1));
                float diff = fabsf(lap_p) - fabsf(lap_t);
                acc = fmaf(diff, diff, acc);
            }
        }
    }
    // block reduction -> double atomic
#pragma unroll
    for (int o = 16; o; o >>= 1) acc += __shfl_down_sync(0xffffffffu, acc, o);
    __shared__ float ws[8];
    int lane = threadIdx.x & 31, wid = threadIdx.x >> 5;
    if (lane == 0) ws[wid] = acc;
    __syncthreads();
    if (wid == 0) {
        acc = (lane < 8) ? ws[lane] : 0.f;
#pragma unroll
        for (int o = 4; o; o >>= 1) acc += __shfl_down_sync(0xffffffffu, acc, o);
        if (lane == 0) atomicAdd(&g_acc, (double)acc);
    }
}

__global__ void finalize_kernel(float* __restrict__ out) {
    out[0] = (float)(g_acc * (1.0 / NELEM));
}

extern "C" void kernel_launch(void* const* d_in, const int* in_sizes, int n_in,
                              void* d_out, int out_size) {
    const float* logits  = (const float*)d_in[0];
    const int*   targets = (const int*)d_in[1];
    float* out = (float*)d_out;

    zero_acc_kernel<<<1, 1>>>();
    softmax_kernel<<<NQ / 256, 256>>>(logits);
    loss_kernel<<<NQ / 256, 256>>>(targets);
    finalize_kernel<<<1, 1>>>(out);
}